// round 16
// baseline (speedup 1.0000x reference)
#include <cuda_runtime.h>
#include <cstdint>
#include <math.h>

// ---------------------------------------------------------------------------
// Problem constants (shapes are fixed by the reference)
// ---------------------------------------------------------------------------
#define BATCH    8
#define SEQ      2048
#define DMODEL   1024
#define DK       512
#define DV       512
#define DOUT     1024
#define NTOK     (BATCH * SEQ)              // 16384
#define NS       ((size_t)NTOK * DK)        // 8388608 elems per (NTOK,512) buffer

// d_out layout: out (B,S,DOUT) | residual (B,S,DK) | attn (B,S,S)
#define OUT_OFF    0
#define RES_OFF    ((size_t)BATCH * SEQ * DOUT)                 // 16777216
#define ATTN_OFF   (RES_OFF + (size_t)BATCH * SEQ * DK)         // 25165824

#define INV_TEMP 0.044194173824159216f       // 1/sqrt(512)

// Scratch: qn | kn | vn | out_attn | h1   (each NTOK x 512 fp32)
__device__ float g_scratch[5 * NS];

// ---------------------------------------------------------------------------
// TF32 helpers
// ---------------------------------------------------------------------------
__device__ __forceinline__ float f2tf(float x) {
    uint32_t u;
    asm("cvt.rna.tf32.f32 %0, %1;" : "=r"(u) : "f"(x));
    return __uint_as_float(u);
}
__device__ __forceinline__ uint32_t fu(float x) { return __float_as_uint(x); }

__device__ __forceinline__ void mma_tf32(float c[4], const uint32_t a[4], const uint32_t b[2]) {
    asm volatile(
        "mma.sync.aligned.m16n8k8.row.col.f32.tf32.tf32.f32 "
        "{%0,%1,%2,%3}, {%4,%5,%6,%7}, {%8,%9}, {%0,%1,%2,%3};\n"
        : "+f"(c[0]), "+f"(c[1]), "+f"(c[2]), "+f"(c[3])
        : "r"(a[0]), "r"(a[1]), "r"(a[2]), "r"(a[3]), "r"(b[0]), "r"(b[1]));
}

// ---------------------------------------------------------------------------
// Generic TF32 GEMM:  C[z] = A[z] @ B[z] (+bias) (+relu)
//   A: row-major M x K (lda = K)
//   BT=false: B row-major K x N (ldb = N)
//   BT=true : logical B[k][n] = Bg[n*K + k]   (i.e. C = A @ Bg^T, Bg row-major N x K)
// Tiles: 128x64x16, 256 threads (8 warps in 4x2 grid, 32x32 per warp).
// EPI: 0 none, 1 +bias, 2 relu(+bias)
// All dims are exact multiples of the tiles (checked against problem shapes).
// ---------------------------------------------------------------------------
template<int EPI, bool BT>
__global__ __launch_bounds__(256)
void gemm_kernel(const float* __restrict__ A, const float* __restrict__ B,
                 const float* __restrict__ bias, float* __restrict__ C,
                 int N, int K, long long sA, long long sB, long long sC)
{
    __shared__ __align__(16) float As[2][128 * 20];  // [m][k], stride 20 (pad)
    __shared__ __align__(16) float Bs[2][1280];      // !BT: [k][n] stride 72 ; BT: [n][k] stride 20

    const int tid  = threadIdx.x;
    const int warp = tid >> 5, lane = tid & 31;
    const int gid  = lane >> 2, tig = lane & 3;
    const int wm   = (warp >> 1) * 32;
    const int wn   = (warp & 1) * 32;

    const size_t z = blockIdx.z;
    const float* Ab = A + (size_t)z * sA + (size_t)blockIdx.y * 128 * K;
    const float* Bb = BT ? (B + (size_t)z * sB + (size_t)blockIdx.x * 64 * K)
                         : (B + (size_t)z * sB + (size_t)blockIdx.x * 64);

    const int am  = tid >> 2;          // 0..63  (A rows, 2 iters of 64)
    const int ak  = (tid & 3) * 4;     // k offset within 16
    const int bk  = tid >> 4;          // 0..15  (!BT: B k-row)
    const int bn4 = (tid & 15) * 4;    // !BT: n offset within 64

    float acc[2][4][4];
#pragma unroll
    for (int i = 0; i < 2; i++)
#pragma unroll
        for (int j = 0; j < 4; j++)
#pragma unroll
            for (int c = 0; c < 4; c++) acc[i][j][c] = 0.f;

    float4 pa0, pa1, pb;

    auto ldg = [&](int k0) {
        pa0 = *(const float4*)&Ab[(size_t)am * K + k0 + ak];
        pa1 = *(const float4*)&Ab[(size_t)(am + 64) * K + k0 + ak];
        if (BT) pb = *(const float4*)&Bb[(size_t)am * K + k0 + ak];   // n=am rows 0..63
        else    pb = *(const float4*)&Bb[(size_t)(k0 + bk) * N + bn4];
    };
    auto sts = [&](int buf) {
        float* a = &As[buf][0];
        *(float4*)&a[am * 20 + ak] =
            make_float4(f2tf(pa0.x), f2tf(pa0.y), f2tf(pa0.z), f2tf(pa0.w));
        *(float4*)&a[(am + 64) * 20 + ak] =
            make_float4(f2tf(pa1.x), f2tf(pa1.y), f2tf(pa1.z), f2tf(pa1.w));
        float* b = &Bs[buf][0];
        float4 cb = make_float4(f2tf(pb.x), f2tf(pb.y), f2tf(pb.z), f2tf(pb.w));
        if (BT) *(float4*)&b[am * 20 + ak] = cb;     // [n][k] stride 20
        else    *(float4*)&b[bk * 72 + bn4] = cb;    // [k][n] stride 72
    };
    auto compute = [&](int buf) {
#pragma unroll
        for (int s = 0; s < 2; s++) {
            const int kk = s * 8;
            uint32_t a[2][4], b[4][2];
#pragma unroll
            for (int mt = 0; mt < 2; mt++) {
                int r0 = (wm + mt * 16 + gid) * 20 + kk + tig;
                a[mt][0] = fu(As[buf][r0]);
                a[mt][1] = fu(As[buf][r0 + 8 * 20]);
                a[mt][2] = fu(As[buf][r0 + 4]);
                a[mt][3] = fu(As[buf][r0 + 8 * 20 + 4]);
            }
#pragma unroll
            for (int nt = 0; nt < 4; nt++) {
                int col = wn + nt * 8 + gid;
                if (BT) {
                    b[nt][0] = fu(Bs[buf][col * 20 + kk + tig]);
                    b[nt][1] = fu(Bs[buf][col * 20 + kk + tig + 4]);
                } else {
                    b[nt][0] = fu(Bs[buf][(kk + tig) * 72 + col]);
                    b[nt][1] = fu(Bs[buf][(kk + tig + 4) * 72 + col]);
                }
            }
#pragma unroll
            for (int mt = 0; mt < 2; mt++)
#pragma unroll
                for (int nt = 0; nt < 4; nt++)
                    mma_tf32(acc[mt][nt], a[mt], b[nt]);
        }
    };

    const int KT = K / 16;
    ldg(0);
    sts(0);
    __syncthreads();
    int cur = 0;
    for (int kt = 0; kt < KT; kt++) {
        if (kt + 1 < KT) ldg((kt + 1) * 16);
        compute(cur);
        if (kt + 1 < KT) {
            sts(cur ^ 1);
            __syncthreads();
            cur ^= 1;
        }
    }

    // Epilogue
    const int m0 = blockIdx.y * 128, n0 = blockIdx.x * 64;
    float* Cb = C + (size_t)z * sC;
#pragma unroll
    for (int mt = 0; mt < 2; mt++) {
#pragma unroll
        for (int nt = 0; nt < 4; nt++) {
            int row = m0 + wm + mt * 16 + gid;
            int col = n0 + wn + nt * 8 + tig * 2;
            float2 v0 = make_float2(acc[mt][nt][0], acc[mt][nt][1]);
            float2 v1 = make_float2(acc[mt][nt][2], acc[mt][nt][3]);
            if (EPI >= 1) {
                float2 bb = *(const float2*)&bias[col];
                v0.x += bb.x; v0.y += bb.y;
                v1.x += bb.x; v1.y += bb.y;
            }
            if (EPI == 2) {
                v0.x = fmaxf(v0.x, 0.f); v0.y = fmaxf(v0.y, 0.f);
                v1.x = fmaxf(v1.x, 0.f); v1.y = fmaxf(v1.y, 0.f);
            }
            *(float2*)&Cb[(size_t)row * N + col]       = v0;
            *(float2*)&Cb[(size_t)(row + 8) * N + col] = v1;
        }
    }
}

// ---------------------------------------------------------------------------
// LayerNorm over rows of 512, affine, eps=1e-6; optional trailing scale (1/TEMP)
// 1 block = 1 row, 128 threads x 4 elems.
// ---------------------------------------------------------------------------
__global__ __launch_bounds__(128)
void ln_kernel(const float* __restrict__ src, const float* __restrict__ g,
               const float* __restrict__ bt, float* __restrict__ dst, float scale)
{
    const int t = threadIdx.x;
    const int warp = t >> 5, lane = t & 31;
    const size_t base = (size_t)blockIdx.x * 512;
    __shared__ float red[4];

    float4 x = *(const float4*)&src[base + t * 4];
    float s = x.x + x.y + x.z + x.w;
#pragma unroll
    for (int o = 16; o > 0; o >>= 1) s += __shfl_xor_sync(0xffffffff, s, o);
    if (lane == 0) red[warp] = s;
    __syncthreads();
    float mean = (red[0] + red[1] + red[2] + red[3]) * (1.f / 512.f);

    float4 d = make_float4(x.x - mean, x.y - mean, x.z - mean, x.w - mean);
    float q = d.x * d.x + d.y * d.y + d.z * d.z + d.w * d.w;
#pragma unroll
    for (int o = 16; o > 0; o >>= 1) q += __shfl_xor_sync(0xffffffff, q, o);
    __syncthreads();
    if (lane == 0) red[warp] = q;
    __syncthreads();
    float var = (red[0] + red[1] + red[2] + red[3]) * (1.f / 512.f);
    float r = rsqrtf(var + 1e-6f);

    float4 gg = *(const float4*)&g[t * 4];
    float4 bb = *(const float4*)&bt[t * 4];
    float4 o;
    o.x = (d.x * r * gg.x + bb.x) * scale;
    o.y = (d.y * r * gg.y + bb.y) * scale;
    o.z = (d.z * r * gg.z + bb.z) * scale;
    o.w = (d.w * r * gg.w + bb.w) * scale;
    *(float4*)&dst[base + t * 4] = o;
}

// ---------------------------------------------------------------------------
// Masked softmax over rows of 2048, in place. 1 block = 1 row, 256 thr x 8.
// mask has identical flat indexing ((B,S,S) int32).
// ---------------------------------------------------------------------------
__global__ __launch_bounds__(256)
void softmax_kernel(float* __restrict__ attn, const int* __restrict__ mask)
{
    const size_t base = (size_t)blockIdx.x * 2048;
    const int t = threadIdx.x;
    const int warp = t >> 5, lane = t & 31;
    __shared__ float red[8];

    float v[8];
#pragma unroll
    for (int i = 0; i < 8; i++) {
        int j = t + i * 256;
        float s = attn[base + j];
        v[i] = (mask[base + j] == 0) ? -1e9f : s;
    }
    float mx = v[0];
#pragma unroll
    for (int i = 1; i < 8; i++) mx = fmaxf(mx, v[i]);
#pragma unroll
    for (int o = 16; o > 0; o >>= 1) mx = fmaxf(mx, __shfl_xor_sync(0xffffffff, mx, o));
    if (lane == 0) red[warp] = mx;
    __syncthreads();
    mx = red[0];
#pragma unroll
    for (int i = 1; i < 8; i++) mx = fmaxf(mx, red[i]);

    float sum = 0.f;
#pragma unroll
    for (int i = 0; i < 8; i++) { v[i] = __expf(v[i] - mx); sum += v[i]; }
#pragma unroll
    for (int o = 16; o > 0; o >>= 1) sum += __shfl_xor_sync(0xffffffff, sum, o);
    __syncthreads();
    if (lane == 0) red[warp] = sum;
    __syncthreads();
    sum = red[0] + red[1] + red[2] + red[3] + red[4] + red[5] + red[6] + red[7];
    float inv = 1.f / sum;
#pragma unroll
    for (int i = 0; i < 8; i++) attn[base + t + i * 256] = v[i] * inv;
}

// ---------------------------------------------------------------------------
// Host launcher
// ---------------------------------------------------------------------------
extern "C" void kernel_launch(void* const* d_in, const int* in_sizes, int n_in,
                              void* d_out, int out_size)
{
    const float* q    = (const float*)d_in[0];
    const float* k    = (const float*)d_in[1];
    const float* v    = (const float*)d_in[2];
    const int*   mask = (const int*)  d_in[3];
    const float* Wq   = (const float*)d_in[4];
    const float* bq   = (const float*)d_in[5];
    const float* Wk   = (const float*)d_in[6];
    const float* bk   = (const float*)d_in[7];
    const float* Wv   = (const float*)d_in[8];
    const float* bv   = (const float*)d_in[9];
    const float* g_q  = (const float*)d_in[10];
    const float* be_q = (const float*)d_in[11];
    const float* g_k  = (const float*)d_in[12];
    const float* be_k = (const float*)d_in[13];
    const float* g_v  = (const float*)d_in[14];
    const float* be_v = (const float*)d_in[15];
    const float* W1   = (const float*)d_in[16];
    const float* b1   = (const float*)d_in[17];
    const float* W2   = (const float*)d_in[18];
    const float* b2   = (const float*)d_in[19];

    float* scratch = nullptr;
    cudaGetSymbolAddress((void**)&scratch, g_scratch);
    float* qn  = scratch;
    float* kn  = scratch + NS;
    float* vn  = scratch + 2 * NS;
    float* oat = scratch + 3 * NS;
    float* h1  = scratch + 4 * NS;

    float* out0  = (float*)d_out + OUT_OFF;
    float* resid = (float*)d_out + RES_OFF;
    float* attn  = (float*)d_out + ATTN_OFF;

    const dim3 blk(256);

    // 1. QKV projections (+bias). qp -> residual region of d_out directly.
    gemm_kernel<1, false><<<dim3(DK / 64, NTOK / 128, 1), blk>>>(
        q, Wq, bq, resid, DK, DMODEL, 0, 0, 0);
    gemm_kernel<1, false><<<dim3(DK / 64, NTOK / 128, 1), blk>>>(
        k, Wk, bk, kn, DK, DMODEL, 0, 0, 0);
    gemm_kernel<1, false><<<dim3(DV / 64, NTOK / 128, 1), blk>>>(
        v, Wv, bv, vn, DV, DMODEL, 0, 0, 0);

    // 2. LayerNorms (q gets 1/TEMP folded in; k,v in place)
    ln_kernel<<<NTOK, 128>>>(resid, g_q, be_q, qn, INV_TEMP);
    ln_kernel<<<NTOK, 128>>>(kn, g_k, be_k, kn, 1.f);
    ln_kernel<<<NTOK, 128>>>(vn, g_v, be_v, vn, 1.f);

    // 3. scores = (qn/TEMP) @ kn^T  per batch -> attn region of d_out
    gemm_kernel<0, true><<<dim3(SEQ / 64, SEQ / 128, BATCH), blk>>>(
        qn, kn, nullptr, attn, SEQ, DK,
        (long long)SEQ * DK, (long long)SEQ * DK, (long long)SEQ * SEQ);

    // 4. masked softmax in place (final attn output)
    softmax_kernel<<<NTOK, 256>>>(attn, mask);

    // 5. out_attn = attn @ vn  per batch
    gemm_kernel<0, false><<<dim3(DV / 64, SEQ / 128, BATCH), blk>>>(
        attn, vn, nullptr, oat, DV, SEQ,
        (long long)SEQ * SEQ, (long long)SEQ * DV, (long long)SEQ * DV);

    // 6. MLP: h1 = relu(oat @ W1 + b1); out = h1 @ W2 + b2
    gemm_kernel<2, false><<<dim3(DV / 64, NTOK / 128, 1), blk>>>(
        oat, W1, b1, h1, DV, DV, 0, 0, 0);
    gemm_kernel<1, false><<<dim3(DOUT / 64, NTOK / 128, 1), blk>>>(
        h1, W2, b2, out0, DOUT, DV, 0, 0, 0);
}